// round 16
// baseline (speedup 1.0000x reference)
#include <cuda_runtime.h>
#include <cstdint>
#include <cstddef>

// Problem constants
#define Bq 2
#define Nq 8192
#define Cq 32
#define Kq 16
#define Rq 4
#define Hq 512
#define CFq 106
#define KP 112                 // padded K for GEMMs (7 chunks of 16)
#define CKq (Bq*Nq*Kq)         // 262144 total (n,k) columns
#define NRq (Bq*Nq*Rq)         // 65536 total (n,r) columns
#define NBq (Bq*Nq)            // 16384 points
#define OF_BASE (Bq*Nq*Rq*3)   // 196608 floats of coarse_xyz before output_feature

// ---------------- scratch (device globals; no allocation) ----------------
__device__ int   g_idx[Bq*Nq*Kq];                  // knn indices, sorted by (d, idx)
__device__ float g_fmat[(size_t)KP*CKq];           // tf32-rounded Fmat, rows 106..111 zero
__device__ float g_whlf[8*7*2048];                 // [Wh;Wl] pre-swizzled A-operand image
__device__ float g_wgf[4*7*2048];                  // Wg pre-swizzled
__device__ float g_g[(size_t)NBq*Hq*4];            // tf32-rounded g point-major [pt][h][r]
__device__ float g_lmax[(size_t)NBq*Hq];           // max_k relu(l) : [pt][h]
__device__ float g_spart[(size_t)16*NBq*64];       // score partials [slab][pt][r][k]
__device__ float g_zero4[4] = {0.0f, 0.0f, 0.0f, 0.0f};

// TF32 rounding (emulates cuBLAS/tensor-core operand conversion).
__device__ __forceinline__ float tf32r(float x) {
    uint32_t u;
    asm("cvt.rna.tf32.f32 %0, %1;" : "=r"(u) : "f"(x));
    return __uint_as_float(u);
}

// order-preserving float->uint key
__device__ __forceinline__ unsigned fkey(float d) {
    unsigned u = __float_as_uint(d);
    return (u & 0x80000000u) ? ~u : (u | 0x80000000u);
}

__device__ __forceinline__ void mma_tf32(float& c0, float& c1, float& c2, float& c3,
                                         uint32_t a0, uint32_t a1, uint32_t a2, uint32_t a3,
                                         uint32_t b0, uint32_t b1) {
    asm volatile("mma.sync.aligned.m16n8k8.row.col.f32.tf32.tf32.f32 "
                 "{%0,%1,%2,%3}, {%4,%5,%6,%7}, {%8,%9}, {%0,%1,%2,%3};"
                 : "+f"(c0), "+f"(c1), "+f"(c2), "+f"(c3)
                 : "r"(a0), "r"(a1), "r"(a2), "r"(a3), "r"(b0), "r"(b1));
}

__device__ __forceinline__ uint32_t s2u(const void* p) {
    uint32_t a;
    asm("{ .reg .u64 t; cvta.to.shared.u64 t, %1; cvt.u32.u64 %0, t; }" : "=r"(a) : "l"(p));
    return a;
}
__device__ __forceinline__ void cpa16(uint32_t dst, const float* src) {
    unsigned long long g = __cvta_generic_to_global(src);
    asm volatile("cp.async.cg.shared.global [%0], [%1], 16;" :: "r"(dst), "l"(g));
}
__device__ __forceinline__ void cpa4(uint32_t dst, const float* src) {
    unsigned long long g = __cvta_generic_to_global(src);
    asm volatile("cp.async.ca.shared.global [%0], [%1], 4;" :: "r"(dst), "l"(g));
}
#define CP_COMMIT() asm volatile("cp.async.commit_group;" ::: "memory")
#define CP_WAIT2()  asm volatile("cp.async.wait_group 2;" ::: "memory")

// ---------------- K0: prep weights into A-operand fragment image -----------
__global__ __launch_bounds__(256) void prep_weights(const float* __restrict__ Wh,
                                                    const float* __restrict__ Wl,
                                                    const float* __restrict__ Wg) {
    int i = blockIdx.x * blockDim.x + threadIdx.x;   // 0 .. 12*7*2048-1
    if (i >= 12*7*2048) return;
    int tile = i / 14336;
    int rem  = i - tile*14336;
    int ch   = rem >> 11;
    int pos  = rem & 2047;
    int mtile = pos >> 8;
    int kstep = (pos >> 7) & 1;
    int idx   = pos & 127;
    int fragp = idx >> 2;            // agid*4 + atig
    int inner = idx & 3;             // amhi + 2*akhi
    int agid = fragp >> 2, atig = fragp & 3;
    int amhi = inner & 1,  akhi = inner >> 1;
    int rt = (tile < 8) ? tile : (tile - 8);
    int row = rt*128 + mtile*16 + amhi*8 + agid;
    int cf  = ch*16 + kstep*8 + akhi*4 + atig;
    float v = 0.0f;
    if (cf < CFq) {
        if (tile < 8) v = (row < 512) ? Wh[row*CFq + cf] : Wl[(row-512)*CFq + cf];
        else          v = Wg[row*CFq + cf];
    }
    if (tile < 8) g_whlf[(tile*7 + ch)*2048 + pos] = tf32r(v);
    else          g_wgf[((tile-8)*7 + ch)*2048 + pos] = tf32r(v);
}

// ---------------- K1: KNN — smem-tiled candidates, register top-16 --------
#define TS 2048
__global__ __launch_bounds__(256) void knn_kernel(const float* __restrict__ xyz) {
    __shared__ float sp[TS*3];
    int tid = threadIdx.x;
    int wid = tid >> 5, lane = tid & 31;
    int gp = blockIdx.x * 8 + wid;
    int b = gp >> 13;
    int n = gp & (Nq - 1);
    const float* xb = xyz + (size_t)b * Nq * 3;
    float qx = xb[n*3+0], qy = xb[n*3+1], qz = xb[n*3+2];
    float sqn = __fmaf_rn(qz, qz, __fmaf_rn(qy, qy, __fmul_rn(qx, qx)));

    unsigned long long key[Kq];
#pragma unroll
    for (int i = 0; i < Kq; i++) key[i] = ~0ull;

    for (int tile = 0; tile < Nq/TS; tile++) {
        __syncthreads();
        for (int i = tid; i < TS*3; i += 256) sp[i] = xb[tile*(TS*3) + i];
        __syncthreads();
#pragma unroll 1
        for (int m = lane; m < TS; m += 32) {
            float px = sp[m*3+0], py = sp[m*3+1], pz = sp[m*3+2];
            int mg = tile*TS + m;
            float sqm = __fmaf_rn(pz, pz, __fmaf_rn(py, py, __fmul_rn(px, px)));
            float dot = __fmaf_rn(qz, pz, __fmaf_rn(qy, py, __fmul_rn(qx, px)));
            float d = __fsub_rn(__fadd_rn(sqn, sqm), __fmul_rn(2.0f, dot));
            unsigned long long c = (((unsigned long long)fkey(d)) << 32) | (unsigned)mg;
            if (mg == n) c = ~0ull;
            if (c < key[Kq-1]) {
#pragma unroll
                for (int j = Kq-1; j > 0; j--)
                    key[j] = (c < key[j-1]) ? key[j-1] : ((c < key[j]) ? c : key[j]);
                key[0] = (c < key[0]) ? c : key[0];
            }
        }
    }

#pragma unroll 1
    for (int t = 0; t < Kq; t++) {
        unsigned long long mk = key[0];
#pragma unroll
        for (int off = 16; off; off >>= 1) {
            unsigned long long o = __shfl_xor_sync(0xffffffffu, mk, off);
            if (o < mk) mk = o;
        }
        if (key[0] == mk) {
#pragma unroll
            for (int j = 0; j < Kq-1; j++) key[j] = key[j+1];
            key[Kq-1] = ~0ull;
        }
        if (lane == 0) g_idx[gp * Kq + t] = (int)(unsigned)(mk & 0xffffffffu);
    }
}

// ---------------- K2: build Fmat (tf32-rounded, padded rows zero) ----------
__global__ __launch_bounds__(256) void fmat_kernel(const float* __restrict__ xyz,
                                                   const float* __restrict__ f) {
    int j = blockIdx.x * blockDim.x + threadIdx.x;
    int n = (j >> 4) & (Nq - 1);
    int b = j >> 17;
    int m = g_idx[j];
    const float* xb = xyz + (size_t)b * Nq * 3;
    float cx = xb[n*3+0], cy = xb[n*3+1], cz = xb[n*3+2];
    float px = xb[m*3+0], py = xb[m*3+1], pz = xb[m*3+2];
    float dx = px - cx, dy = py - cy, dz = pz - cz;
    float dist = sqrtf(dx*dx + dy*dy + dz*dz);

    const float* fb = f + (size_t)b * Cq * Nq;
#pragma unroll 4
    for (int c = 0; c < Cq; c++) {
        float gf  = fb[c*Nq + m];
        float cfv = fb[c*Nq + n];
        g_fmat[(size_t)c*CKq + j]          = tf32r(gf);
        g_fmat[(size_t)(Cq + c)*CKq + j]   = tf32r(cfv);
        g_fmat[(size_t)(2*Cq + c)*CKq + j] = tf32r(cfv - gf);
    }
    g_fmat[(size_t)96*CKq + j]  = tf32r(dx);
    g_fmat[(size_t)97*CKq + j]  = tf32r(dy);
    g_fmat[(size_t)98*CKq + j]  = tf32r(dz);
    g_fmat[(size_t)99*CKq + j]  = tf32r(px);
    g_fmat[(size_t)100*CKq + j] = tf32r(py);
    g_fmat[(size_t)101*CKq + j] = tf32r(pz);
    g_fmat[(size_t)102*CKq + j] = tf32r(cx);
    g_fmat[(size_t)103*CKq + j] = tf32r(cy);
    g_fmat[(size_t)104*CKq + j] = tf32r(cz);
    g_fmat[(size_t)105*CKq + j] = tf32r(dist);
#pragma unroll
    for (int c = 106; c < KP; c++) g_fmat[(size_t)c*CKq + j] = 0.0f;
}

// ---------------- K3: TF32 mma GEMM, cp.async 4-stage pipeline (dyn smem) --
// MODE 0: [Wh;Wl] @ Fmat. h rows -> fused score partials; l rows -> g_lmax.
// MODE 1: Wg @ gather(Fmat) -> g_g (rounded).
#define STAGES 4
#define GEMM_SMEM (STAGES*2048*2*sizeof(float))   // 64 KB dynamic
template <int MODE>
__global__ __launch_bounds__(256, 2) void gemm_mma_kernel(
    const float* __restrict__ b0, const float* __restrict__ b1,
    const int* __restrict__ rind)
{
    extern __shared__ float smem_dyn[];
    float* Asm = smem_dyn;                 // [STAGES][2048]
    float* Bsm = smem_dyn + STAGES*2048;   // [STAGES][2048]

    int row0 = blockIdx.x * 128;
    int col0 = blockIdx.y * 128;
    bool lmode = (MODE == 0) && (row0 >= Hq);

    const float* Wf = (MODE == 0) ? (g_whlf + (size_t)blockIdx.x*7*2048)
                                  : (g_wgf  + (size_t)blockIdx.x*7*2048);
    const float* bias = lmode ? (b1 + (row0 - Hq)) : (b0 + row0);

    int tid  = threadIdx.x;
    int wid  = tid >> 5;
    int lane = tid & 31;
    int warp_m = wid >> 1;
    int warp_n = wid & 1;
    int gid = lane >> 2;
    int tig = lane & 3;

    // B fill mapping: thread -> col (t&127), k quads b in {2q, 2q+1}, q=t>>7
    int n_f = tid & 127;
    int bq0 = (tid >> 7) * 2;            // 0 or 2
    int ntileB = n_f >> 3;
    int bposB = (n_f & 7) * 16;
    int colB = col0 + n_f;

    int fmbase = 0; size_t rbase = 0;
    if (MODE == 1) {
        int nb = colB >> 2;
        int rr = colB & 3;
        int bb = nb >> 13;
        int nn = nb & (Nq - 1);
        rbase  = ((size_t)bb*CFq*Nq + nn)*4 + rr;
        fmbase = nb*16;
    }

    uint32_t sAs = s2u(Asm);
    uint32_t sBs = s2u(Bsm);
    uint32_t aDst = sAs + tid*32;                       // within-stage offset
    uint32_t bDst = sBs + (ntileB*128 + bposB)*4;

#define ISSUE_CHUNK(CH) do {                                                             \
    if ((CH) < 7) {                                                                      \
        int kb = (CH)*16; int st = (CH) & (STAGES-1);                                    \
        const float* asrc = Wf + (CH)*2048 + tid*8;                                      \
        cpa16(aDst + st*8192, asrc);                                                     \
        cpa16(aDst + st*8192 + 16, asrc + 4);                                            \
        _Pragma("unroll") for (int qi = 0; qi < 2; qi++) {                               \
            int bb_ = bq0 + qi;                                                          \
            _Pragma("unroll") for (int a = 0; a < 4; a++) {                              \
                int cf = kb + bb_ + a*4;                                                 \
                const float* src;                                                        \
                if (MODE == 0) src = &g_fmat[(size_t)cf*CKq + colB];                     \
                else if (cf < CFq) {                                                     \
                    int ri = rind[rbase + (size_t)cf*(Nq*4)];                            \
                    src = &g_fmat[(size_t)cf*CKq + fmbase + ri];                         \
                } else src = g_zero4;                                                    \
                cpa4(bDst + st*8192 + (bb_*4 + a)*4, src);                               \
            }                                                                            \
        }                                                                                \
    }                                                                                    \
    CP_COMMIT();                                                                         \
  } while (0)

    float acc[2][8][4];
#pragma unroll
    for (int mi = 0; mi < 2; mi++)
#pragma unroll
        for (int ni = 0; ni < 8; ni++)
#pragma unroll
            for (int q = 0; q < 4; q++) acc[mi][ni][q] = 0.0f;

    ISSUE_CHUNK(0);
    ISSUE_CHUNK(1);
    ISSUE_CHUNK(2);

#pragma unroll 1
    for (int ch = 0; ch < 7; ch++) {
        int cur = ch & (STAGES-1);
        CP_WAIT2();                 // oldest group (chunk ch) complete
        __syncthreads();
        ISSUE_CHUNK(ch + 3);        // fills slot (ch+3)&3; prev occupant consumed at ch-1
        // A fragments for both ksteps
        uint32_t a[2][2][4];
#pragma unroll
        for (int mi = 0; mi < 2; mi++)
#pragma unroll
            for (int ks = 0; ks < 2; ks++) {
                float4 av = *(const float4*)&Asm[cur*2048 + (warp_m*2 + mi)*256 + ks*128 + lane*4];
                a[mi][ks][0] = __float_as_uint(av.x); a[mi][ks][1] = __float_as_uint(av.y);
                a[mi][ks][2] = __float_as_uint(av.z); a[mi][ks][3] = __float_as_uint(av.w);
            }
#pragma unroll
        for (int ni = 0; ni < 8; ni++) {
            float4 bv = *(const float4*)&Bsm[cur*2048 + (warp_n*8 + ni)*128 + lane*4];
            uint32_t b00 = __float_as_uint(bv.x), b01 = __float_as_uint(bv.y);
            uint32_t b10 = __float_as_uint(bv.z), b11 = __float_as_uint(bv.w);
#pragma unroll
            for (int mi = 0; mi < 2; mi++) {
                mma_tf32(acc[mi][ni][0], acc[mi][ni][1], acc[mi][ni][2], acc[mi][ni][3],
                         a[mi][0][0], a[mi][0][1], a[mi][0][2], a[mi][0][3], b00, b01);
                mma_tf32(acc[mi][ni][0], acc[mi][ni][1], acc[mi][ni][2], acc[mi][ni][3],
                         a[mi][1][0], a[mi][1][1], a[mi][1][2], a[mi][1][3], b10, b11);
            }
        }
    }
#undef ISSUE_CHUNK

    // bias + relu
#pragma unroll
    for (int mi = 0; mi < 2; mi++) {
        int rl0 = warp_m*32 + mi*16 + gid;
        float bb_lo = bias[rl0];
        float bb_hi = bias[rl0 + 8];
#pragma unroll
        for (int ni = 0; ni < 8; ni++) {
            acc[mi][ni][0] = fmaxf(acc[mi][ni][0] + bb_lo, 0.0f);
            acc[mi][ni][1] = fmaxf(acc[mi][ni][1] + bb_lo, 0.0f);
            acc[mi][ni][2] = fmaxf(acc[mi][ni][2] + bb_hi, 0.0f);
            acc[mi][ni][3] = fmaxf(acc[mi][ni][3] + bb_hi, 0.0f);
        }
    }

    if (MODE == 1) {
        // g point-major, stored tf32-rounded (only consumer is scores)
#pragma unroll
        for (int mi = 0; mi < 2; mi++) {
            int row = row0 + warp_m*32 + mi*16 + gid;
#pragma unroll
            for (int ni = 0; ni < 8; ni++) {
                int col = col0 + warp_n*64 + ni*8 + tig*2;
                int pt = col >> 2, r = col & 3;
                *(float2*)&g_g[((size_t)pt*Hq + row)*4 + r] =
                    make_float2(tf32r(acc[mi][ni][0]), tf32r(acc[mi][ni][1]));
                *(float2*)&g_g[((size_t)pt*Hq + row + 8)*4 + r] =
                    make_float2(tf32r(acc[mi][ni][2]), tf32r(acc[mi][ni][3]));
            }
        }
    } else if (!lmode) {
        // fused score partials: s[r][k] = sum_rows g[row][r] * tf32r(h[row][k])
        int slab = blockIdx.x*4 + warp_m;          // 16 row-slabs of 32 rows
        int rowbase = row0 + warp_m*32 + gid;
#pragma unroll 1
        for (int p = 0; p < 4; p++) {
            int pt = (col0 >> 4) + warp_n*4 + p;
            float4 grow[4];
#pragma unroll
            for (int q = 0; q < 4; q++)
                grow[q] = *(const float4*)&g_g[((size_t)pt*Hq + rowbase + q*8)*4];
            float s[4][4];
#pragma unroll
            for (int r = 0; r < 4; r++)
#pragma unroll
                for (int kk = 0; kk < 4; kk++) s[r][kk] = 0.0f;
#pragma unroll
            for (int q = 0; q < 4; q++) {
                int mi = q >> 1, hi = q & 1;
                float h0 = tf32r(acc[mi][2*p  ][hi*2+0]);
                float h1 = tf32r(acc[mi][2*p  ][hi*2+1]);
                float h2 = tf32r(acc[mi][2*p+1][hi*2+0]);
                float h3 = tf32r(acc[mi][2*p+1][hi*2+1]);
                float gr[4] = {grow[q].x, grow[q].y, grow[q].z, grow[q].w};
#pragma unroll
                for (int r = 0; r < 4; r++) {
                    s[r][0] = fmaf(gr[r], h0, s[r][0]);
                    s[r][1] = fmaf(gr[r], h1, s[r][1]);
                    s[r][2] = fmaf(gr[r], h2, s[r][2]);
                    s[r][3] = fmaf(gr[r], h3, s[r][3]);
                }
            }
            // reduce over gid (lane bits 2..4)
#pragma unroll
            for (int off = 4; off <= 16; off <<= 1)
#pragma unroll
                for (int r = 0; r < 4; r++)
#pragma unroll
                    for (int kk = 0; kk < 4; kk++)
                        s[r][kk] += __shfl_xor_sync(0xffffffffu, s[r][kk], off);
            if (gid == 0) {
                size_t base = ((size_t)slab*NBq + pt)*64;
#pragma unroll
                for (int r = 0; r < 4; r++) {
                    *(float2*)&g_spart[base + r*16 + 2*tig]     = make_float2(s[r][0], s[r][1]);
                    *(float2*)&g_spart[base + r*16 + 8 + 2*tig] = make_float2(s[r][2], s[r][3]);
                }
            }
        }
    } else {
        // l rows: max over the 16 k-columns of each point (4 points per warp)
#pragma unroll
        for (int mi = 0; mi < 2; mi++) {
#pragma unroll
            for (int p = 0; p < 4; p++) {
                float vlo = fmaxf(fmaxf(acc[mi][2*p][0], acc[mi][2*p][1]),
                                  fmaxf(acc[mi][2*p+1][0], acc[mi][2*p+1][1]));
                float vhi = fmaxf(fmaxf(acc[mi][2*p][2], acc[mi][2*p][3]),
                                  fmaxf(acc[mi][2*p+1][2], acc[mi][2*p+1][3]));
#pragma unroll
                for (int off = 1; off <= 2; off <<= 1) {
                    vlo = fmaxf(vlo, __shfl_xor_sync(0xffffffffu, vlo, off));
                    vhi = fmaxf(vhi, __shfl_xor_sync(0xffffffffu, vhi, off));
                }
                if (tig == 0) {
                    int pt = (col0 >> 4) + warp_n*4 + p;
                    int lrow = (row0 - Hq) + warp_m*32 + mi*16 + gid;
                    g_lmax[(size_t)pt*Hq + lrow]     = vlo;
                    g_lmax[(size_t)pt*Hq + lrow + 8] = vhi;
                }
            }
        }
    }
}

// ---------------- K4: finalize (sum partials, softmax, aff, outputs) -------
__global__ __launch_bounds__(128) void finalize_kernel(float* __restrict__ out) {
    __shared__ float gx[3][16];

    int nb = blockIdx.x;
    int b = nb >> 13;
    int n = nb & (Nq - 1);
    int tid = threadIdx.x;
    size_t cb = (size_t)nb * Kq;

    // l_prime
    for (int h = tid; h < Hq; h += 128) {
        float lmx = g_lmax[(size_t)nb*Hq + h];
        float4 o; o.x = lmx; o.y = lmx; o.z = lmx; o.w = lmx;
        *(float4*)&out[OF_BASE + (((size_t)b*515 + h)*Nq + n)*Rq] = o;
    }
    if (tid < 48) {
        int c = tid >> 4, k = tid & 15;
        gx[c][k] = g_fmat[(size_t)(99 + c)*CKq + cb + k];   // already tf32-rounded
    }
    __syncthreads();

    if (tid < 64) {
        int r = tid >> 4, k = tid & 15;
        float sv = 0.0f;
#pragma unroll
        for (int slab = 0; slab < 16; slab++)
            sv += g_spart[((size_t)slab*NBq + nb)*64 + tid];
        float mx = sv;
#pragma unroll
        for (int off = 8; off; off >>= 1) mx = fmaxf(mx, __shfl_xor_sync(0xffffffffu, mx, off));
        float e = expf(sv - mx);
        float sum = e;
#pragma unroll
        for (int off = 8; off; off >>= 1) sum += __shfl_xor_sync(0xffffffffu, sum, off);
        float sim = tf32r(e / sum);
        float a0 = sim * gx[0][k];
        float a1 = sim * gx[1][k];
        float a2 = sim * gx[2][k];
#pragma unroll
        for (int off = 8; off; off >>= 1) {
            a0 += __shfl_xor_sync(0xffffffffu, a0, off);
            a1 += __shfl_xor_sync(0xffffffffu, a1, off);
            a2 += __shfl_xor_sync(0xffffffffu, a2, off);
        }
        if (k == 0) {
            size_t cbase = ((size_t)b*(Nq*Rq) + (size_t)n*Rq + r) * 3;
            out[cbase + 0] = a0;
            out[cbase + 1] = a1;
            out[cbase + 2] = a2;
            out[OF_BASE + (((size_t)b*515 + 512)*Nq + n)*Rq + r] = a0;
            out[OF_BASE + (((size_t)b*515 + 513)*Nq + n)*Rq + r] = a1;
            out[OF_BASE + (((size_t)b*515 + 514)*Nq + n)*Rq + r] = a2;
        }
    }
}

// ---------------- launch ----------------
extern "C" void kernel_launch(void* const* d_in, const int* in_sizes, int n_in,
                              void* d_out, int out_size) {
    const float* xyz  = (const float*)d_in[0];
    const float* f    = (const float*)d_in[1];
    const float* Wg   = (const float*)d_in[2];
    const float* bg   = (const float*)d_in[3];
    const float* Wh   = (const float*)d_in[4];
    const float* bh   = (const float*)d_in[5];
    const float* Wl   = (const float*)d_in[6];
    const float* bl   = (const float*)d_in[7];
    const int*   rind = (const int*)d_in[8];
    float* out = (float*)d_out;

    static int smem_set = 0;
    if (!smem_set) {
        cudaFuncSetAttribute(gemm_mma_kernel<0>, cudaFuncAttributeMaxDynamicSharedMemorySize, (int)GEMM_SMEM);
        cudaFuncSetAttribute(gemm_mma_kernel<1>, cudaFuncAttributeMaxDynamicSharedMemorySize, (int)GEMM_SMEM);
        smem_set = 1;
    }

    prep_weights<<<(12*7*2048 + 255)/256, 256>>>(Wh, Wl, Wg);
    knn_kernel<<<NBq/8, 256>>>(xyz);
    fmat_kernel<<<CKq/256, 256>>>(xyz, f);
    gemm_mma_kernel<1><<<dim3(Hq/128, NRq/128), 256, GEMM_SMEM>>>(bg, bg, rind);
    gemm_mma_kernel<0><<<dim3((2*Hq)/128, CKq/128), 256, GEMM_SMEM>>>(bh, bl, nullptr);
    finalize_kernel<<<NBq, 128>>>(out);
}

// round 17
// speedup vs baseline: 1.1522x; 1.1522x over previous
#include <cuda_runtime.h>
#include <cstdint>
#include <cstddef>

// Problem constants
#define Bq 2
#define Nq 8192
#define Cq 32
#define Kq 16
#define Rq 4
#define Hq 512
#define CFq 106
#define KP 112                 // padded K for GEMMs (7 chunks of 16)
#define CKq (Bq*Nq*Kq)         // 262144 total (n,k) columns
#define NRq (Bq*Nq*Rq)         // 65536 total (n,r) columns
#define NBq (Bq*Nq)            // 16384 points
#define OF_BASE (Bq*Nq*Rq*3)   // 196608 floats of coarse_xyz before output_feature

// ---------------- scratch (device globals; no allocation) ----------------
__device__ int   g_idx[Bq*Nq*Kq];                  // knn indices, sorted by (d, idx)
__device__ float g_fmat[(size_t)KP*CKq];           // tf32-rounded Fmat, rows 106..111 zero
__device__ float g_whlf[8*7*2048];                 // [Wh;Wl] pre-swizzled A-operand image
__device__ float g_wgf[4*7*2048];                  // Wg pre-swizzled
__device__ float g_g[(size_t)NBq*Hq*4];            // tf32-rounded g point-major [pt][h][r]
__device__ float g_lmax[(size_t)NBq*Hq];           // max_k relu(l) : [pt][h]
__device__ float g_spart[(size_t)16*NBq*64];       // score partials [slab][pt][r][k]

// TF32 rounding (emulates cuBLAS/tensor-core operand conversion).
__device__ __forceinline__ float tf32r(float x) {
    uint32_t u;
    asm("cvt.rna.tf32.f32 %0, %1;" : "=r"(u) : "f"(x));
    return __uint_as_float(u);
}

// order-preserving float->uint key
__device__ __forceinline__ unsigned fkey(float d) {
    unsigned u = __float_as_uint(d);
    return (u & 0x80000000u) ? ~u : (u | 0x80000000u);
}

__device__ __forceinline__ void mma_tf32(float& c0, float& c1, float& c2, float& c3,
                                         uint32_t a0, uint32_t a1, uint32_t a2, uint32_t a3,
                                         uint32_t b0, uint32_t b1) {
    asm volatile("mma.sync.aligned.m16n8k8.row.col.f32.tf32.tf32.f32 "
                 "{%0,%1,%2,%3}, {%4,%5,%6,%7}, {%8,%9}, {%0,%1,%2,%3};"
                 : "+f"(c0), "+f"(c1), "+f"(c2), "+f"(c3)
                 : "r"(a0), "r"(a1), "r"(a2), "r"(a3), "r"(b0), "r"(b1));
}

// ---------------- K0: prep weights into A-operand fragment image -----------
__global__ __launch_bounds__(256) void prep_weights(const float* __restrict__ Wh,
                                                    const float* __restrict__ Wl,
                                                    const float* __restrict__ Wg) {
    int i = blockIdx.x * blockDim.x + threadIdx.x;   // 0 .. 12*7*2048-1
    if (i >= 12*7*2048) return;
    int tile = i / 14336;
    int rem  = i - tile*14336;
    int ch   = rem >> 11;
    int pos  = rem & 2047;
    int mtile = pos >> 8;
    int kstep = (pos >> 7) & 1;
    int idx   = pos & 127;
    int fragp = idx >> 2;            // agid*4 + atig
    int inner = idx & 3;             // amhi + 2*akhi
    int agid = fragp >> 2, atig = fragp & 3;
    int amhi = inner & 1,  akhi = inner >> 1;
    int rt = (tile < 8) ? tile : (tile - 8);
    int row = rt*128 + mtile*16 + amhi*8 + agid;
    int cf  = ch*16 + kstep*8 + akhi*4 + atig;
    float v = 0.0f;
    if (cf < CFq) {
        if (tile < 8) v = (row < 512) ? Wh[row*CFq + cf] : Wl[(row-512)*CFq + cf];
        else          v = Wg[row*CFq + cf];
    }
    if (tile < 8) g_whlf[(tile*7 + ch)*2048 + pos] = tf32r(v);
    else          g_wgf[((tile-8)*7 + ch)*2048 + pos] = tf32r(v);
}

// ---------------- K1: KNN — smem tiles + lazy warp threshold ---------------
#define TS 2048
__global__ __launch_bounds__(256) void knn_kernel(const float* __restrict__ xyz) {
    __shared__ float sp[TS*3];
    __shared__ float sq[TS];
    int tid = threadIdx.x;
    int wid = tid >> 5, lane = tid & 31;
    int gp = blockIdx.x * 8 + wid;
    int b = gp >> 13;
    int n = gp & (Nq - 1);
    const float* xb = xyz + (size_t)b * Nq * 3;
    float qx = xb[n*3+0], qy = xb[n*3+1], qz = xb[n*3+2];
    float sqn = __fmaf_rn(qz, qz, __fmaf_rn(qy, qy, __fmul_rn(qx, qx)));

    unsigned long long key[Kq];
#pragma unroll
    for (int i = 0; i < Kq; i++) key[i] = ~0ull;
    unsigned long long thr = ~0ull;   // lazy warp-shared prune threshold
    int cnt = 0;

    for (int tile = 0; tile < Nq/TS; tile++) {
        __syncthreads();
        for (int i = tid; i < TS*3; i += 256) sp[i] = xb[tile*(TS*3) + i];
        __syncthreads();
        for (int i = tid; i < TS; i += 256) {
            float x = sp[i*3+0], y = sp[i*3+1], z = sp[i*3+2];
            sq[i] = __fmaf_rn(z, z, __fmaf_rn(y, y, __fmul_rn(x, x)));
        }
        __syncthreads();
#pragma unroll 1
        for (int m = lane; m < TS; m += 32) {
            float px = sp[m*3+0], py = sp[m*3+1], pz = sp[m*3+2];
            int mg = tile*TS + m;
            float sqm = sq[m];
            float dot = __fmaf_rn(qz, pz, __fmaf_rn(qy, py, __fmul_rn(qx, px)));
            float d = __fsub_rn(__fadd_rn(sqn, sqm), __fmul_rn(2.0f, dot));
            unsigned long long c = (((unsigned long long)fkey(d)) << 32) | (unsigned)mg;
            if (mg == n) c = ~0ull;
            if (c < thr) {   // provably safe prune: thr >= final union 16th
#pragma unroll
                for (int j = Kq-1; j > 0; j--)
                    key[j] = (c < key[j-1]) ? key[j-1] : ((c < key[j]) ? c : key[j]);
                key[0] = (c < key[0]) ? c : key[0];
            }
            if ((++cnt & 15) == 0) {      // uniform across lanes
                unsigned long long t = key[Kq-1];
#pragma unroll
                for (int off = 16; off; off >>= 1) {
                    unsigned long long o = __shfl_xor_sync(0xffffffffu, t, off);
                    if (o < t) t = o;
                }
                thr = t;
            }
        }
    }

#pragma unroll 1
    for (int t = 0; t < Kq; t++) {
        unsigned long long mk = key[0];
#pragma unroll
        for (int off = 16; off; off >>= 1) {
            unsigned long long o = __shfl_xor_sync(0xffffffffu, mk, off);
            if (o < mk) mk = o;
        }
        if (key[0] == mk) {
#pragma unroll
            for (int j = 0; j < Kq-1; j++) key[j] = key[j+1];
            key[Kq-1] = ~0ull;
        }
        if (lane == 0) g_idx[gp * Kq + t] = (int)(unsigned)(mk & 0xffffffffu);
    }
}

// ---------------- K2: build Fmat (tf32-rounded, padded rows zero) ----------
__global__ __launch_bounds__(256) void fmat_kernel(const float* __restrict__ xyz,
                                                   const float* __restrict__ f) {
    int j = blockIdx.x * blockDim.x + threadIdx.x;
    int n = (j >> 4) & (Nq - 1);
    int b = j >> 17;
    int m = g_idx[j];
    const float* xb = xyz + (size_t)b * Nq * 3;
    float cx = xb[n*3+0], cy = xb[n*3+1], cz = xb[n*3+2];
    float px = xb[m*3+0], py = xb[m*3+1], pz = xb[m*3+2];
    float dx = px - cx, dy = py - cy, dz = pz - cz;
    float dist = sqrtf(dx*dx + dy*dy + dz*dz);

    const float* fb = f + (size_t)b * Cq * Nq;
#pragma unroll 4
    for (int c = 0; c < Cq; c++) {
        float gf  = fb[c*Nq + m];
        float cfv = fb[c*Nq + n];
        g_fmat[(size_t)c*CKq + j]          = tf32r(gf);
        g_fmat[(size_t)(Cq + c)*CKq + j]   = tf32r(cfv);
        g_fmat[(size_t)(2*Cq + c)*CKq + j] = tf32r(cfv - gf);
    }
    g_fmat[(size_t)96*CKq + j]  = tf32r(dx);
    g_fmat[(size_t)97*CKq + j]  = tf32r(dy);
    g_fmat[(size_t)98*CKq + j]  = tf32r(dz);
    g_fmat[(size_t)99*CKq + j]  = tf32r(px);
    g_fmat[(size_t)100*CKq + j] = tf32r(py);
    g_fmat[(size_t)101*CKq + j] = tf32r(pz);
    g_fmat[(size_t)102*CKq + j] = tf32r(cx);
    g_fmat[(size_t)103*CKq + j] = tf32r(cy);
    g_fmat[(size_t)104*CKq + j] = tf32r(cz);
    g_fmat[(size_t)105*CKq + j] = tf32r(dist);
#pragma unroll
    for (int c = 106; c < KP; c++) g_fmat[(size_t)c*CKq + j] = 0.0f;
}

// ---------------- K3: TF32 mma GEMM (R14 mainloop + hoisted addressing) ----
// MODE 0: [Wh;Wl] @ Fmat. h rows -> fused score partials; l rows -> g_lmax.
// MODE 1: Wg @ gather(Fmat) -> g_g (rounded).
template <int MODE>
__global__ __launch_bounds__(256, 2) void gemm_mma_kernel(
    const float* __restrict__ b0, const float* __restrict__ b1,
    const int* __restrict__ rind)
{
    __shared__ float As[2][8][2][128];   // [buf][mtile][kstep][frag pos]
    __shared__ float Bs[2][16][128];     // [buf][ntile][ col8*16 + (k&3)*4 + (k>>2) ]

    int row0 = blockIdx.x * 128;
    int col0 = blockIdx.y * 128;
    bool lmode = (MODE == 0) && (row0 >= Hq);

    const float* Wf = (MODE == 0) ? (g_whlf + (size_t)blockIdx.x*7*2048)
                                  : (g_wgf  + (size_t)blockIdx.x*7*2048);
    const float* bias = lmode ? (b1 + (row0 - Hq)) : (b0 + row0);

    int tid  = threadIdx.x;
    int wid  = tid >> 5;
    int lane = tid & 31;
    int warp_m = wid >> 1;
    int warp_n = wid & 1;
    int gid = lane >> 2;
    int tig = lane & 3;

    // B fill mapping: thread -> col (t&127), k quads b in {2q, 2q+1}, q=t>>7
    int n_f = tid & 127;
    int bq0 = (tid >> 7) * 2;            // 0 or 2
    int ntileB = n_f >> 3;
    int bposB = (n_f & 7) * 16;
    int colB = col0 + n_f;

    // hoisted fill bases
    const float* bptr0;                  // MODE 0 stream / MODE 1 fmat window
    const int*   rptr = nullptr;
    if (MODE == 0) {
        bptr0 = g_fmat + (size_t)bq0*CKq + colB;
    } else {
        int nb = colB >> 2;
        int rr = colB & 3;
        int bb = nb >> 13;
        int nn = nb & (Nq - 1);
        rptr  = rind + ((size_t)bb*CFq*Nq + nn)*4 + rr + (size_t)bq0*(size_t)(Nq*4);
        bptr0 = g_fmat + (size_t)nb*16 + (size_t)bq0*CKq;
    }

    float4 pA[2], pB[2];

#define LOAD_CHUNK(CH) do {                                                              \
    const float4* asrc = (const float4*)(Wf + (CH)*2048) + tid*2;                        \
    pA[0] = asrc[0]; pA[1] = asrc[1];                                                    \
    size_t boff = (size_t)((CH)*16) * CKq;                                               \
    _Pragma("unroll") for (int qi = 0; qi < 2; qi++) {                                   \
        float vv[4];                                                                     \
        _Pragma("unroll") for (int a = 0; a < 4; a++) {                                  \
            if (MODE == 0) vv[a] = bptr0[boff + (size_t)(qi + 4*a)*CKq];                 \
            else {                                                                       \
                int cf = (CH)*16 + bq0 + qi + 4*a;                                       \
                if (cf < CFq) {                                                          \
                    int ri = rptr[(size_t)((CH)*16)*(Nq*4) + (size_t)(qi + 4*a)*(Nq*4)]; \
                    vv[a] = bptr0[boff + (size_t)(qi + 4*a)*CKq + ri];                   \
                } else vv[a] = 0.0f;                                                     \
            }                                                                            \
        }                                                                                \
        pB[qi] = make_float4(vv[0], vv[1], vv[2], vv[3]);                                \
    }                                                                                    \
  } while (0)

#define STORE_CHUNK(BUF) do {                                                            \
    float4* adst = (float4*)&As[BUF][0][0][0] + tid*2;                                   \
    adst[0] = pA[0]; adst[1] = pA[1];                                                    \
    *(float4*)&Bs[BUF][ntileB][bposB + (bq0    )*4] = pB[0];                             \
    *(float4*)&Bs[BUF][ntileB][bposB + (bq0 + 1)*4] = pB[1];                             \
  } while (0)

    float acc[2][8][4];
#pragma unroll
    for (int mi = 0; mi < 2; mi++)
#pragma unroll
        for (int ni = 0; ni < 8; ni++)
#pragma unroll
            for (int q = 0; q < 4; q++) acc[mi][ni][q] = 0.0f;

    LOAD_CHUNK(0);
    STORE_CHUNK(0);
    __syncthreads();

#pragma unroll 1
    for (int ch = 0; ch < 7; ch++) {
        int cur = ch & 1;
        if (ch < 6) LOAD_CHUNK(ch + 1);
        // A fragments for both ksteps
        uint32_t a[2][2][4];
#pragma unroll
        for (int mi = 0; mi < 2; mi++)
#pragma unroll
            for (int ks = 0; ks < 2; ks++) {
                float4 av = *(const float4*)&As[cur][warp_m*2 + mi][ks][lane*4];
                a[mi][ks][0] = __float_as_uint(av.x); a[mi][ks][1] = __float_as_uint(av.y);
                a[mi][ks][2] = __float_as_uint(av.z); a[mi][ks][3] = __float_as_uint(av.w);
            }
#pragma unroll
        for (int ni = 0; ni < 8; ni++) {
            float4 bv = *(const float4*)&Bs[cur][(warp_n*8 + ni)][lane*4];
            uint32_t b00 = __float_as_uint(bv.x), b01 = __float_as_uint(bv.y);
            uint32_t b10 = __float_as_uint(bv.z), b11 = __float_as_uint(bv.w);
            // ks-outer / mi-inner: same per-acc order (ks0 then ks1), RAW dist 2
            mma_tf32(acc[0][ni][0], acc[0][ni][1], acc[0][ni][2], acc[0][ni][3],
                     a[0][0][0], a[0][0][1], a[0][0][2], a[0][0][3], b00, b01);
            mma_tf32(acc[1][ni][0], acc[1][ni][1], acc[1][ni][2], acc[1][ni][3],
                     a[1][0][0], a[1][0][1], a[1][0][2], a[1][0][3], b00, b01);
            mma_tf32(acc[0][ni][0], acc[0][ni][1], acc[0][ni][2], acc[0][ni][3],
                     a[0][1][0], a[0][1][1], a[0][1][2], a[0][1][3], b10, b11);
            mma_tf32(acc[1][ni][0], acc[1][ni][1], acc[1][ni][2], acc[1][ni][3],
                     a[1][1][0], a[1][1][1], a[1][1][2], a[1][1][3], b10, b11);
        }
        if (ch < 6) STORE_CHUNK(cur ^ 1);
        __syncthreads();
    }
#undef LOAD_CHUNK
#undef STORE_CHUNK

    // bias + relu
#pragma unroll
    for (int mi = 0; mi < 2; mi++) {
        int rl0 = warp_m*32 + mi*16 + gid;
        float bb_lo = bias[rl0];
        float bb_hi = bias[rl0 + 8];
#pragma unroll
        for (int ni = 0; ni < 8; ni++) {
            acc[mi][ni][0] = fmaxf(acc[mi][ni][0] + bb_lo, 0.0f);
            acc[mi][ni][1] = fmaxf(acc[mi][ni][1] + bb_lo, 0.0f);
            acc[mi][ni][2] = fmaxf(acc[mi][ni][2] + bb_hi, 0.0f);
            acc[mi][ni][3] = fmaxf(acc[mi][ni][3] + bb_hi, 0.0f);
        }
    }

    if (MODE == 1) {
        // g point-major, stored tf32-rounded (only consumer is scores)
#pragma unroll
        for (int mi = 0; mi < 2; mi++) {
            int row = row0 + warp_m*32 + mi*16 + gid;
#pragma unroll
            for (int ni = 0; ni < 8; ni++) {
                int col = col0 + warp_n*64 + ni*8 + tig*2;
                int pt = col >> 2, r = col & 3;
                *(float2*)&g_g[((size_t)pt*Hq + row)*4 + r] =
                    make_float2(tf32r(acc[mi][ni][0]), tf32r(acc[mi][ni][1]));
                *(float2*)&g_g[((size_t)pt*Hq + row + 8)*4 + r] =
                    make_float2(tf32r(acc[mi][ni][2]), tf32r(acc[mi][ni][3]));
            }
        }
    } else if (!lmode) {
        // fused score partials: s[r][k] = sum_rows g[row][r] * tf32r(h[row][k])
        int slab = blockIdx.x*4 + warp_m;          // 16 row-slabs of 32 rows
        int rowbase = row0 + warp_m*32 + gid;
#pragma unroll 1
        for (int p = 0; p < 4; p++) {
            int pt = (col0 >> 4) + warp_n*4 + p;
            float4 grow[4];
#pragma unroll
            for (int q = 0; q < 4; q++)
                grow[q] = *(const float4*)&g_g[((size_t)pt*Hq + rowbase + q*8)*4];
            float s[4][4];
#pragma unroll
            for (int r = 0; r < 4; r++)
#pragma unroll
                for (int kk = 0; kk < 4; kk++) s[r][kk] = 0.0f;
#pragma unroll
            for (int q = 0; q < 4; q++) {
                int mi = q >> 1, hi = q & 1;
                float h0 = tf32r(acc[mi][2*p  ][hi*2+0]);
                float h1 = tf32r(acc[mi][2*p  ][hi*2+1]);
                float h2 = tf32r(acc[mi][2*p+1][hi*2+0]);
                float h3 = tf32r(acc[mi][2*p+1][hi*2+1]);
                float gr[4] = {grow[q].x, grow[q].y, grow[q].z, grow[q].w};
#pragma unroll
                for (int r = 0; r < 4; r++) {
                    s[r][0] = fmaf(gr[r], h0, s[r][0]);
                    s[r][1] = fmaf(gr[r], h1, s[r][1]);
                    s[r][2] = fmaf(gr[r], h2, s[r][2]);
                    s[r][3] = fmaf(gr[r], h3, s[r][3]);
                }
            }
            // reduce over gid (lane bits 2..4)
#pragma unroll
            for (int off = 4; off <= 16; off <<= 1)
#pragma unroll
                for (int r = 0; r < 4; r++)
#pragma unroll
                    for (int kk = 0; kk < 4; kk++)
                        s[r][kk] += __shfl_xor_sync(0xffffffffu, s[r][kk], off);
            if (gid == 0) {
                size_t base = ((size_t)slab*NBq + pt)*64;
#pragma unroll
                for (int r = 0; r < 4; r++) {
                    *(float2*)&g_spart[base + r*16 + 2*tig]     = make_float2(s[r][0], s[r][1]);
                    *(float2*)&g_spart[base + r*16 + 8 + 2*tig] = make_float2(s[r][2], s[r][3]);
                }
            }
        }
    } else {
        // l rows: max over the 16 k-columns of each point (4 points per warp)
#pragma unroll
        for (int mi = 0; mi < 2; mi++) {
#pragma unroll
            for (int p = 0; p < 4; p++) {
                float vlo = fmaxf(fmaxf(acc[mi][2*p][0], acc[mi][2*p][1]),
                                  fmaxf(acc[mi][2*p+1][0], acc[mi][2*p+1][1]));
                float vhi = fmaxf(fmaxf(acc[mi][2*p][2], acc[mi][2*p][3]),
                                  fmaxf(acc[mi][2*p+1][2], acc[mi][2*p+1][3]));
#pragma unroll
                for (int off = 1; off <= 2; off <<= 1) {
                    vlo = fmaxf(vlo, __shfl_xor_sync(0xffffffffu, vlo, off));
                    vhi = fmaxf(vhi, __shfl_xor_sync(0xffffffffu, vhi, off));
                }
                if (tig == 0) {
                    int pt = (col0 >> 4) + warp_n*4 + p;
                    int lrow = (row0 - Hq) + warp_m*32 + mi*16 + gid;
                    g_lmax[(size_t)pt*Hq + lrow]     = vlo;
                    g_lmax[(size_t)pt*Hq + lrow + 8] = vhi;
                }
            }
        }
    }
}

// ---------------- K4: finalize (sum partials, softmax, aff, outputs) -------
__global__ __launch_bounds__(128) void finalize_kernel(float* __restrict__ out) {
    __shared__ float gx[3][16];

    int nb = blockIdx.x;
    int b = nb >> 13;
    int n = nb & (Nq - 1);
    int tid = threadIdx.x;
    size_t cb = (size_t)nb * Kq;

    // l_prime
    for (int h = tid; h < Hq; h += 128) {
        float lmx = g_lmax[(size_t)nb*Hq + h];
        float4 o; o.x = lmx; o.y = lmx; o.z = lmx; o.w = lmx;
        *(float4*)&out[OF_BASE + (((size_t)b*515 + h)*Nq + n)*Rq] = o;
    }
    if (tid < 48) {
        int c = tid >> 4, k = tid & 15;
        gx[c][k] = g_fmat[(size_t)(99 + c)*CKq + cb + k];   // already tf32-rounded
    }
    __syncthreads();

    if (tid < 64) {
        int r = tid >> 4, k = tid & 15;
        float sv = 0.0f;
#pragma unroll
        for (int slab = 0; slab < 16; slab++)
            sv += g_spart[((size_t)slab*NBq + nb)*64 + tid];
        float mx = sv;
#pragma unroll
        for (int off = 8; off; off >>= 1) mx = fmaxf(mx, __shfl_xor_sync(0xffffffffu, mx, off));
        float e = expf(sv - mx);
        float sum = e;
#pragma unroll
        for (int off = 8; off; off >>= 1) sum += __shfl_xor_sync(0xffffffffu, sum, off);
        float sim = tf32r(e / sum);
        float a0 = sim * gx[0][k];
        float a1 = sim * gx[1][k];
        float a2 = sim * gx[2][k];
#pragma unroll
        for (int off = 8; off; off >>= 1) {
            a0 += __shfl_xor_sync(0xffffffffu, a0, off);
            a1 += __shfl_xor_sync(0xffffffffu, a1, off);
            a2 += __shfl_xor_sync(0xffffffffu, a2, off);
        }
        if (k == 0) {
            size_t cbase = ((size_t)b*(Nq*Rq) + (size_t)n*Rq + r) * 3;
            out[cbase + 0] = a0;
            out[cbase + 1] = a1;
            out[cbase + 2] = a2;
            out[OF_BASE + (((size_t)b*515 + 512)*Nq + n)*Rq + r] = a0;
            out[OF_BASE + (((size_t)b*515 + 513)*Nq + n)*Rq + r] = a1;
            out[OF_BASE + (((size_t)b*515 + 514)*Nq + n)*Rq + r] = a2;
        }
    }
}

// ---------------- launch ----------------
extern "C" void kernel_launch(void* const* d_in, const int* in_sizes, int n_in,
                              void* d_out, int out_size) {
    const float* xyz  = (const float*)d_in[0];
    const float* f    = (const float*)d_in[1];
    const float* Wg   = (const float*)d_in[2];
    const float* bg   = (const float*)d_in[3];
    const float* Wh   = (const float*)d_in[4];
    const float* bh   = (const float*)d_in[5];
    const float* Wl   = (const float*)d_in[6];
    const float* bl   = (const float*)d_in[7];
    const int*   rind = (const int*)d_in[8];
    float* out = (float*)d_out;

    prep_weights<<<(12*7*2048 + 255)/256, 256>>>(Wh, Wl, Wg);
    knn_kernel<<<NBq/8, 256>>>(xyz);
    fmat_kernel<<<CKq/256, 256>>>(xyz, f);
    gemm_mma_kernel<1><<<dim3(Hq/128, NRq/128), 256>>>(bg, bg, rind);       // g first
    gemm_mma_kernel<0><<<dim3((2*Hq)/128, CKq/128), 256>>>(bh, bl, nullptr); // h/l + scores
    finalize_kernel<<<NBq, 128>>>(out);
}